// round 17
// baseline (speedup 1.0000x reference)
#include <cuda_runtime.h>

#define NNODES 3000
#define BATCH  16
#define FEAT   43
#define NREL   3
#define NBUCKET (NREL*NNODES)
#define ROWS   (BATCH*NNODES)     // 48000
#define GBN    2                  // nodes per block in RGCN kernel (4 CTAs/SM)
#define OBSTR  129                // padded stride for obs staging (bank-conflict free)
#define RW     (BATCH*FEAT)       // 688 floats per node-row in [n][b][f] global layout
#define RW2    (RW/2)             // 344 float2 per row
#define RW4    (RW/4)             // 172 float4 per row
#define CHUNK  1000               // buckets per scanA block (9 blocks)

// ---------------- scratch (static __device__, no allocation) ----------------
__device__ __align__(16) float d_x [NNODES*RW];
__device__ __align__(16) float d_h1[NNODES*RW];
__device__ __align__(16) float d_h2[NNODES*RW];
__device__ int   dc_cnt[NBUCKET];
__device__ int   dc_off[NBUCKET+1];
__device__ int   dc_cur[NBUCKET];
__device__ float dc_inv[NBUCKET];
__device__ int   dc_src[96000];
__device__ int   d_bsum[9];

// ---------------- CSR build ----------------
__global__ void k_count(const int* __restrict__ ei, const int* __restrict__ et, int E) {
    int e = blockIdx.x*blockDim.x + threadIdx.x;
    if (e >= E) return;
    atomicAdd(&dc_cnt[et[e]*NNODES + ei[E+e]], 1);
}

// scanA: 9 blocks x 1024 threads; block b scans buckets [b*1000, b*1000+1000)
// writes local-exclusive prefix into dc_off, dc_inv, chunk total into d_bsum[b].
// Also self-zeros dc_cnt for the next graph replay.
__global__ void k_scanA(int E) {
    __shared__ int ws[32];
    int tid = threadIdx.x;
    int lane = tid & 31, warp = tid >> 5;
    int g = blockIdx.x*CHUNK + tid;
    bool act = tid < CHUNK;
    int v = 0;
    if (act) { v = dc_cnt[g]; dc_cnt[g] = 0; }
    int si = v;
    #pragma unroll
    for (int d = 1; d < 32; d <<= 1) {
        int t2 = __shfl_up_sync(0xffffffffu, si, d);
        if (lane >= d) si += t2;
    }
    if (lane == 31) ws[warp] = si;
    __syncthreads();
    if (warp == 0) {
        int w = ws[lane];
        #pragma unroll
        for (int d = 1; d < 32; d <<= 1) {
            int t2 = __shfl_up_sync(0xffffffffu, w, d);
            if (lane >= d) w += t2;
        }
        ws[lane] = w;
    }
    __syncthreads();
    int excl = si - v + (warp > 0 ? ws[warp-1] : 0);
    if (act) {
        dc_off[g] = excl;                      // local prefix; base added in scanB
        dc_inv[g] = 1.0f / (float)(v > 1 ? v : 1);
    }
    if (tid == 0) d_bsum[blockIdx.x] = ws[31]; // chunk total
}

// scanB: finalize offsets with chunk bases; init dc_cur.
__global__ void k_scanB(int E) {
    __shared__ int base[9];
    int tid = threadIdx.x;
    if (tid == 0) {
        int run = 0;
        #pragma unroll
        for (int i = 0; i < 9; i++) { base[i] = run; run += d_bsum[i]; }
    }
    __syncthreads();
    for (int g = tid; g < NBUCKET; g += 1024) {
        int off = dc_off[g] + base[g/CHUNK];
        dc_off[g] = off;
        dc_cur[g] = off;
    }
    if (tid == 0) dc_off[NBUCKET] = E;
}

// ---------------- fused fill + temporal (disjoint role blocks) ----------------
// blocks [0, fillblk): fill role (384 edges each). blocks [fillblk, ...): temporal.
__global__ void __launch_bounds__(384, 2) k_fill_temporal(
    const int* __restrict__ ei, const int* __restrict__ et, int E, int fillblk,
    const float* __restrict__ obs,
    const float* __restrict__ ws1, const float* __restrict__ bs1,
    const float* __restrict__ ws2, const float* __restrict__ bs2,
    const float* __restrict__ wm1, const float* __restrict__ bm1,
    const float* __restrict__ wm2, const float* __restrict__ bm2)
{
    if (blockIdx.x < fillblk) {
        int e = blockIdx.x*384 + threadIdx.x;
        if (e < E) {
            int g = et[e]*NNODES + ei[E+e];
            int p = atomicAdd(&dc_cur[g], 1);
            dc_src[p] = ei[e];
        }
        return;
    }
    // ---- temporal role (round-16 proven body) ----
    extern __shared__ float sm[];
    float* s_ws2t = sm;            // 2880  [t][c][o]
    float* s_wm2t = sm + 2880;     // 1800
    float* s_bs2  = sm + 4680;     // 20
    float* s_bm2  = sm + 4700;     // 20
    float* s_wm1  = sm + 4720;     // 189
    float* s_ws1  = sm + 4909;     // 27
    float* s_bs1  = sm + 4936;     // 3
    float* s_bm1  = sm + 4939;     // 3 (+2 pad)
    float* s_part = sm + 4944;     // 20*128
    float* s_ob   = sm + 7504;     // 150*129
    int tid = threadIdx.x;

    for (int i = tid; i < 2880; i += 384) {
        int o = i/144, c = (i/48)%3, t = i%48;
        s_ws2t[(t*3+c)*20 + o] = __ldg(&ws2[i]);
    }
    for (int i = tid; i < 1800; i += 384) {
        int o = i/90, c = (i/30)%3, t = i%30;
        s_wm2t[(t*3+c)*20 + o] = __ldg(&wm2[i]);
    }
    for (int i = tid; i < 189; i += 384) s_wm1[i] = __ldg(&wm1[i]);
    if (tid < 27) s_ws1[tid] = __ldg(&ws1[tid]);
    if (tid < 3)  { s_bs1[tid] = __ldg(&bs1[tid]); s_bm1[tid] = __ldg(&bm1[tid]); }
    if (tid < 20) { s_bs2[tid] = __ldg(&bs2[tid]); s_bm2[tid] = __ldg(&bm2[tid]); }

    int idx0 = (blockIdx.x - fillblk)*128;
    for (int i = tid; i < 128*150; i += 384) {
        int slot = i/150, rem = i%150, c = rem/50, t = rem%50;
        int g = idx0 + slot; int b = g/NNODES, n = g%NNODES;
        s_ob[(c*50+t)*OBSTR + slot] = __ldg(&obs[(((size_t)(b*3+c))*NNODES + n)*50 + t]);
    }
    __syncthreads();

    int role = tid >> 7;
    int slot = tid & 127;
    const float* myob = s_ob + slot;
    int gme = idx0 + slot;
    int bb = gme / NNODES, nn = gme % NNODES;
    float* xo = d_x + (size_t)nn*RW + bb*FEAT;

    if (role == 0) {
        #pragma unroll
        for (int c = 0; c < 3; c++) {
            float m = myob[(c*50)*OBSTR];
            for (int t = 1; t < 50; t++) m = fmaxf(m, myob[(c*50+t)*OBSTR]);
            xo[40+c] = fmaxf(m, 0.f);
        }
        float acc[20];
        #pragma unroll
        for (int o = 0; o < 20; o++) acc[o] = s_bs2[o];
        float x0[3], x1[3];
        #pragma unroll
        for (int c = 0; c < 3; c++) { x0[c] = myob[(c*50+0)*OBSTR]; x1[c] = myob[(c*50+1)*OBSTR]; }
        for (int t = 0; t < 48; t++) {
            float x2[3];
            #pragma unroll
            for (int c = 0; c < 3; c++) x2[c] = myob[(c*50+t+2)*OBSTR];
            float s1[3];
            #pragma unroll
            for (int co = 0; co < 3; co++) {
                float v = s_bs1[co];
                #pragma unroll
                for (int ci = 0; ci < 3; ci++)
                    v += x0[ci]*s_ws1[(co*3+ci)*3+0] + x1[ci]*s_ws1[(co*3+ci)*3+1] + x2[ci]*s_ws1[(co*3+ci)*3+2];
                s1[co] = fmaxf(v, 0.f);
            }
            const float4* wt4 = (const float4*)(s_ws2t + t*60);
            #pragma unroll
            for (int c = 0; c < 3; c++) {
                float v = s1[c];
                #pragma unroll
                for (int q = 0; q < 5; q++) {
                    float4 w = wt4[c*5 + q];
                    acc[q*4+0] += v*w.x; acc[q*4+1] += v*w.y;
                    acc[q*4+2] += v*w.z; acc[q*4+3] += v*w.w;
                }
            }
            #pragma unroll
            for (int c = 0; c < 3; c++) { x0[c] = x1[c]; x1[c] = x2[c]; }
        }
        #pragma unroll
        for (int o = 0; o < 20; o++) xo[o] = fmaxf(acc[o], 0.f);
    }

    float accm[20];
    if (role >= 1) {
        int pass = role - 1;
        #pragma unroll
        for (int o = 0; o < 20; o++) accm[o] = (pass == 0) ? s_bm2[o] : 0.f;
        float m1[3][15];
        #pragma unroll
        for (int co = 0; co < 3; co++)
            #pragma unroll
            for (int tt = 0; tt < 15; tt++) m1[co][tt] = s_bm1[co];
        for (int ci = 0; ci < 3; ci++) {
            for (int k = 0; k < 21; k++) {
                float w0 = s_wm1[(0*3+ci)*21+k];
                float w1 = s_wm1[(1*3+ci)*21+k];
                float w2 = s_wm1[(2*3+ci)*21+k];
                const float* pb = myob + (ci*50 + pass*15 + k)*OBSTR;
                #pragma unroll
                for (int tt = 0; tt < 15; tt++) {
                    float ov = pb[tt*OBSTR];
                    m1[0][tt] += ov*w0; m1[1][tt] += ov*w1; m1[2][tt] += ov*w2;
                }
            }
        }
        #pragma unroll
        for (int tt = 0; tt < 15; tt++) {
            const float4* wt4 = (const float4*)(s_wm2t + (pass*15+tt)*60);
            #pragma unroll
            for (int c = 0; c < 3; c++) {
                float v = fmaxf(m1[c][tt], 0.f);
                #pragma unroll
                for (int q = 0; q < 5; q++) {
                    float4 w = wt4[c*5 + q];
                    accm[q*4+0] += v*w.x; accm[q*4+1] += v*w.y;
                    accm[q*4+2] += v*w.z; accm[q*4+3] += v*w.w;
                }
            }
        }
        if (role == 2) {
            #pragma unroll
            for (int o = 0; o < 20; o++) s_part[o*128 + slot] = accm[o];
        }
    }
    __syncthreads();
    if (role == 1) {
        #pragma unroll
        for (int o = 0; o < 20; o++) {
            float v = accm[o] + s_part[o*128 + slot];
            xo[20+o] = fmaxf(v, 0.f);
        }
    }
}

// ---------------- RGCN layer: 384 threads (48 warps/SM), GBN=2 ----------------
__global__ void __launch_bounds__(384) k_rgcn(int layer,
                       const float* __restrict__ root,
                       const float* __restrict__ rel,
                       const float* __restrict__ bias)
{
    extern __shared__ float sm[];
    float* w_s    = sm;              // 4*1849 = 7396: [root, rel0..2], row-major [f][o]
    float* bias_s = sm + 7396;       // 48 (padded, zeros beyond 43)
    float* s_x    = sm + 7444;       // GBN*RW = 1376
    float* agg_s  = sm + 7444 + GBN*RW;   // [r][nl][RW] = 4128

    const float* xin  = (layer == 0) ? d_x  : d_h1;
    float*       xout = (layer == 0) ? d_h1 : d_h2;

    int tid = threadIdx.x;
    for (int i = tid; i < 1849;   i += 384) w_s[i]       = __ldg(root + i);
    for (int i = tid; i < 3*1849; i += 384) w_s[1849+i]  = __ldg(rel + i);
    if (tid < 48) bias_s[tid] = (tid < FEAT) ? bias[tid] : 0.f;

    int node0 = blockIdx.x * GBN;

    // stage this block's own rows (root term)
    {
        const float4* xr4 = (const float4*)(xin + (size_t)node0*RW);
        float4* sx4 = (float4*)s_x;
        for (int i = tid; i < GBN*RW4; i += 384) sx4[i] = __ldg(xr4 + i);
    }

    // ---- gather: one float2 slot per thread (tid < 344) ----
    const float2* xin2 = (const float2*)xin;
    bool act = tid < RW2;
    #pragma unroll
    for (int nl = 0; nl < GBN; nl++) {
        int n = node0 + nl;
        #pragma unroll
        for (int r = 0; r < NREL; r++) {
            int g  = r*NNODES + n;
            int s_ = dc_off[g], e_ = dc_off[g+1];
            float ax = 0.f, ay = 0.f;
            int e = s_;
            for (; e + 2 <= e_; e += 2) {
                int s0 = __ldg(&dc_src[e])   * RW2;
                int s1 = __ldg(&dc_src[e+1]) * RW2;
                if (act) {
                    float2 v0 = __ldg(xin2 + s0 + tid);
                    float2 v1 = __ldg(xin2 + s1 + tid);
                    ax += v0.x + v1.x; ay += v0.y + v1.y;
                }
            }
            if (e < e_) {
                int s0 = __ldg(&dc_src[e]) * RW2;
                if (act) {
                    float2 v0 = __ldg(xin2 + s0 + tid);
                    ax += v0.x; ay += v0.y;
                }
            }
            if (act) {
                float inv = dc_inv[g];
                float2* ab = (float2*)(agg_s + (r*GBN + nl)*RW);
                float2 wa; wa.x = ax*inv; wa.y = ay*inv;
                ab[tid] = wa;
            }
        }
    }
    __syncthreads();

    // ---- matmul: thread -> (part, nl, b); 12 parts of 4 outputs (o>=43 junk, never stored) ----
    int b    = tid & 15;
    int nl   = (tid >> 4) & 1;
    int part = tid >> 5;          // 0..11 (warp-uniform => w_s reads broadcast)
    int n    = node0 + nl;
    int o0   = part * 4;          // 0..44

    float outv[4];
    #pragma unroll
    for (int oo = 0; oo < 4; oo++) outv[oo] = bias_s[o0 + oo];

    const float* xr = s_x + nl*RW + b*FEAT;
    for (int f = 0; f < FEAT; f++) {
        float xv = xr[f];
        const float* wr = w_s + f*FEAT + o0;
        #pragma unroll
        for (int oo = 0; oo < 4; oo++) outv[oo] += xv * wr[oo];
    }
    #pragma unroll
    for (int r = 0; r < NREL; r++) {
        const float* ar = agg_s + (r*GBN + nl)*RW + b*FEAT;
        const float* wb = w_s + (1 + r)*1849 + o0;
        for (int f = 0; f < FEAT; f++) {
            float av = ar[f];
            const float* wr = wb + f*FEAT;
            #pragma unroll
            for (int oo = 0; oo < 4; oo++) outv[oo] += av * wr[oo];
        }
    }

    float* yo = xout + (size_t)n*RW + b*FEAT;
    #pragma unroll
    for (int oo = 0; oo < 4; oo++) {
        int o = o0 + oo;
        if (o < FEAT) {
            float v = outv[oo];
            yo[o] = v > 0.f ? v : 0.01f*v;     // leaky_relu 0.01
        }
    }
}

// ---------------- head ([n][b][f] layout) ----------------
__global__ void k_head(const float* __restrict__ la, const int* __restrict__ sel,
                       const float* __restrict__ wf, const float* __restrict__ bf,
                       float* __restrict__ out)
{
    __shared__ float sh[501];
    __shared__ float rbuf[16];
    int b = blockIdx.x, t = threadIdx.x;
    if (t == 0) sh[0] = 0.f;                 // cash logit
    if (t < 500) {
        int node = __ldg(&sel[t]);
        float v = __ldg(bf) + __ldg(wf)*__ldg(&la[b*501 + 1 + t]);
        const float* xr = d_x  + (size_t)node*RW + b*FEAT;
        const float* hr = d_h2 + (size_t)node*RW + b*FEAT;
        #pragma unroll
        for (int f = 0; f < FEAT; f++) v += __ldg(&wf[1 + f])  * __ldg(xr + f);
        #pragma unroll
        for (int f = 0; f < FEAT; f++) v += __ldg(&wf[44 + f]) * __ldg(hr + f);
        sh[1 + t] = v;
    }
    __syncthreads();

    float m = -1e30f;
    for (int i = t; i < 501; i += 512) m = fmaxf(m, sh[i]);
    #pragma unroll
    for (int off = 16; off; off >>= 1) m = fmaxf(m, __shfl_xor_sync(0xffffffffu, m, off));
    if ((t & 31) == 0) rbuf[t >> 5] = m;
    __syncthreads();
    if (t == 0) { float mm = rbuf[0]; for (int w = 1; w < 16; w++) mm = fmaxf(mm, rbuf[w]); rbuf[0] = mm; }
    __syncthreads();
    float gm = rbuf[0];
    __syncthreads();

    float ssum = 0.f;
    for (int i = t; i < 501; i += 512) { float e = __expf(sh[i] - gm); sh[i] = e; ssum += e; }
    #pragma unroll
    for (int off = 16; off; off >>= 1) ssum += __shfl_xor_sync(0xffffffffu, ssum, off);
    if ((t & 31) == 0) rbuf[t >> 5] = ssum;
    __syncthreads();
    if (t == 0) { float s2 = 0.f; for (int w = 0; w < 16; w++) s2 += rbuf[w]; rbuf[0] = s2; }
    __syncthreads();
    float invs = 1.0f / rbuf[0];
    for (int i = t; i < 501; i += 512) out[b*501 + i] = sh[i] * invs;
}

// ---------------- launch ----------------
extern "C" void kernel_launch(void* const* d_in, const int* in_sizes, int n_in,
                              void* d_out, int out_size)
{
    const float* obs   = (const float*)d_in[0];
    const float* la    = (const float*)d_in[1];
    const int*   ei    = (const int*)  d_in[2];
    const int*   et    = (const int*)  d_in[3];
    const int*   sel   = (const int*)  d_in[4];
    const float* ws1   = (const float*)d_in[5];
    const float* bs1   = (const float*)d_in[6];
    const float* ws2   = (const float*)d_in[7];
    const float* bs2   = (const float*)d_in[8];
    const float* wm1   = (const float*)d_in[9];
    const float* bm1   = (const float*)d_in[10];
    const float* wm2   = (const float*)d_in[11];
    const float* bm2   = (const float*)d_in[12];
    const float* root1 = (const float*)d_in[13];
    const float* rel1  = (const float*)d_in[14];
    const float* bias1 = (const float*)d_in[15];
    const float* root2 = (const float*)d_in[16];
    const float* rel2  = (const float*)d_in[17];
    const float* bias2 = (const float*)d_in[18];
    const float* wf    = (const float*)d_in[19];
    const float* bf    = (const float*)d_in[20];
    float* out = (float*)d_out;

    int E = in_sizes[3];   // 96000
    int fillblk = (E + 383)/384;   // 250

    int smem_t = (7504 + 150*OBSTR) * (int)sizeof(float);                      // 107416 B
    int smem_r = (7444 + GBN*RW + NREL*GBN*RW) * (int)sizeof(float);           // 51792 B -> 4 CTAs/SM
    cudaFuncSetAttribute(k_fill_temporal, cudaFuncAttributeMaxDynamicSharedMemorySize, smem_t);
    cudaFuncSetAttribute(k_rgcn,          cudaFuncAttributeMaxDynamicSharedMemorySize, smem_r);

    // #0 count (dc_cnt zeroed by previous scanA; BSS-zero on first call)
    k_count<<<(E + 255)/256, 256>>>(ei, et, E);
    // #1, #2 two-level scan
    k_scanA<<<9, 1024>>>(E);
    k_scanB<<<1, 1024>>>(E);
    // #3 fused fill + temporal   (ncu captures launch #3)
    k_fill_temporal<<<fillblk + ROWS/128, 384, smem_t>>>(ei, et, E, fillblk,
        obs, ws1, bs1, ws2, bs2, wm1, bm1, wm2, bm2);
    // #4, #5 RGCN layers
    k_rgcn<<<NNODES/GBN, 384, smem_r>>>(0, root1, rel1, bias1);
    k_rgcn<<<NNODES/GBN, 384, smem_r>>>(1, root2, rel2, bias2);
    // #6 head
    k_head<<<BATCH, 512>>>(la, sel, wf, bf, out);
}